// round 14
// baseline (speedup 1.0000x reference)
#include <cuda_runtime.h>
#include <cuda_fp16.h>

#define NN   50000
#define EE   800000
#define EPAD 850000
#define IN1  192
#define C1   256

// ---------------- scratch (device globals; zero-initialized at load) ----------------
__device__ __half g_xh [NN * IN1];
__device__ __half g_w1t[C1 * IN1];
__device__ __half g_h1h[(size_t)NN * C1];
__device__ float2 g_Es [NN * 8];        // {exp(as1), exp(0.2*as1)}
__device__ float2 g_Ed [NN * 8];        // {exp(ad1), exp(0.2*ad1)}
__device__ float  g_h2 [NN * 8];
__device__ float2 g_P  [NN];            // {exp(a2s), exp(0.2*a2s)}
__device__ float2 g_Q  [NN];            // {exp(a2d), exp(0.2*a2d)}
__device__ int    g_cnt[NN];
__device__ int2   g_seg[NN];
__device__ int    g_csr[EPAD];

#define EMB_B  25000
#define EDGE_B ((EE + 383) / 384)
#define W1T_B  ((C1 * IN1 + 383) / 384)

// ---------------- launch 1: emb+concat (fp16), degree count, W1 transpose ----------------
__global__ void k_front(const float* __restrict__ high, const float* __restrict__ low,
                        const float* __restrict__ Wemb, const float* __restrict__ bemb,
                        const float* __restrict__ W1, const int* __restrict__ ei) {
    int bid = blockIdx.x;
    int tid = threadIdx.y * 192 + threadIdx.x;
    if (bid < EMB_B) {
        __shared__ float ls[2][32];
        int n = bid * 2 + threadIdx.y;
        int c = threadIdx.x;
        if (c < 32) ls[threadIdx.y][c] = low[n * 32 + c];
        __syncthreads();
        if (c < 128) {
            g_xh[n * IN1 + c] = __float2half(high[n * 128 + c]);
        } else {
            int j = c - 128;
            float s = bemb[j];
#pragma unroll
            for (int k = 0; k < 32; k++) s += ls[threadIdx.y][k] * Wemb[k * 64 + j];
            s = s > 0.f ? s : __expf(s) - 1.f;
            g_xh[n * IN1 + c] = __float2half(s);
        }
    } else if (bid < EMB_B + EDGE_B) {
        int e = (bid - EMB_B) * 384 + tid;
        if (e < EE) atomicAdd(&g_cnt[ei[EE + e]], 1);
    } else {
        int j = (bid - EMB_B - EDGE_B) * 384 + tid;
        if (j < C1 * IN1) {
            int k = j >> 8, n = j & 255;
            g_w1t[n * IN1 + k] = __float2half(W1[j]);
        }
    }
}

// ---------------- launch 2: segment assignment scan ----------------
__global__ void __launch_bounds__(1024) k_scan() {
    int t = threadIdx.x;
    int s = 0;
    for (int i = 0; i < 49; i++) {
        int idx = t + i * 1024;
        if (idx < NN) s += g_cnt[idx] + 1;
    }
    int lane = t & 31, wid = t >> 5;
    int v = s;
#pragma unroll
    for (int o = 1; o < 32; o <<= 1) {
        int u = __shfl_up_sync(~0u, v, o);
        if (lane >= o) v += u;
    }
    __shared__ int wsum[32];
    if (lane == 31) wsum[wid] = v;
    __syncthreads();
    if (wid == 0) {
        int w = wsum[lane];
#pragma unroll
        for (int o = 1; o < 32; o <<= 1) {
            int u = __shfl_up_sync(~0u, w, o);
            if (lane >= o) w += u;
        }
        wsum[lane] = w;
    }
    __syncthreads();
    int base = v - s + (wid ? wsum[wid - 1] : 0);
    for (int i = 0; i < 49; i++) {
        int idx = t + i * 1024;
        if (idx < NN) {
            int cnt = g_cnt[idx] + 1;
            g_seg[idx] = make_int2(base, base + cnt);
            g_csr[base] = idx;
            g_cnt[idx] = base + 1;
            base += cnt;
        }
    }
}

// ---------------- launch 3: pipelined fp16 HMMA GEMM + attention epilogue + edge scatter ----------------
__device__ __forceinline__ void ldsm4(unsigned& r0, unsigned& r1, unsigned& r2, unsigned& r3,
                                      unsigned addr) {
    asm volatile("ldmatrix.sync.aligned.m8n8.x4.shared.b16 {%0,%1,%2,%3},[%4];"
                 : "=r"(r0), "=r"(r1), "=r"(r2), "=r"(r3) : "r"(addr));
}
__device__ __forceinline__ void mma16816(float& c0, float& c1, float& c2, float& c3,
                                         unsigned a0, unsigned a1, unsigned a2, unsigned a3,
                                         unsigned b0, unsigned b1) {
    asm volatile("mma.sync.aligned.m16n8k16.row.col.f32.f16.f16.f32 "
                 "{%0,%1,%2,%3},{%4,%5,%6,%7},{%8,%9},{%0,%1,%2,%3};"
                 : "+f"(c0), "+f"(c1), "+f"(c2), "+f"(c3)
                 : "r"(a0), "r"(a1), "r"(a2), "r"(a3), "r"(b0), "r"(b1));
}
__device__ __forceinline__ void cpasync16(unsigned dst, const void* src, int sz) {
    asm volatile("cp.async.ca.shared.global [%0], [%1], 16, %2;"
                 :: "r"(dst), "l"(src), "r"(sz));
}

#define RS       72
#define MAT_B    (128 * RS * 2)
#define STAGE_B  (2 * MAT_B)
#define SMEM_B   (3 * STAGE_B)
#define GEMM_B   782                   // 391 M-tiles x 2 N-tiles
#define SCAT_B   ((EE + 255) / 256)

__global__ void __launch_bounds__(256) k_gemm(const float* __restrict__ a_s,
                                              const float* __restrict__ a_d,
                                              const int* __restrict__ ei) {
    int bid = blockIdx.x;
    int tid = threadIdx.x;
    if (bid >= GEMM_B) {
        // edge scatter blocks (independent of GEMM work)
        int e = (bid - GEMM_B) * 256 + tid;
        if (e < EE) {
            int s = ei[e], d = ei[EE + e];
            int p = atomicAdd(&g_cnt[d], 1);
            g_csr[p] = s;
        }
        return;
    }
    extern __shared__ __half sm[];
    unsigned smBase = (unsigned)__cvta_generic_to_shared(sm);
    int bm = (bid >> 1) * 128, bn = (bid & 1) * 128;
    int lane = tid & 31, wid = tid >> 5;
    int warpM = wid & 1, warpN = wid >> 1;

#pragma unroll
    for (int c = 0; c < 3; c++) {
        unsigned aS = smBase + c * STAGE_B;
        unsigned bS = aS + MAT_B;
#pragma unroll
        for (int i = tid; i < 1024; i += 256) {
            int r = i >> 3, ch = i & 7;
            int m = bm + r;
            const __half* src = &g_xh[(size_t)min(m, NN - 1) * IN1 + c * 64 + ch * 8];
            cpasync16(aS + (r * RS + ch * 8) * 2, src, m < NN ? 16 : 0);
        }
#pragma unroll
        for (int i = tid; i < 1024; i += 256) {
            int r = i >> 3, ch = i & 7;
            cpasync16(bS + (r * RS + ch * 8) * 2, &g_w1t[(bn + r) * IN1 + c * 64 + ch * 8], 16);
        }
        asm volatile("cp.async.commit_group;" ::: "memory");
    }

    float acc[4][4][4];
#pragma unroll
    for (int i = 0; i < 4; i++)
#pragma unroll
        for (int j = 0; j < 4; j++)
#pragma unroll
            for (int q = 0; q < 4; q++) acc[i][j][q] = 0.f;

    unsigned aRow = (unsigned)(warpM * 64 + (lane & 7) + ((lane >> 3) & 1) * 8);
    unsigned bRow = (unsigned)(warpN * 32 + (lane & 7) + (lane >> 4) * 8);

    for (int c = 0; c < 3; c++) {
        if (c == 0)      asm volatile("cp.async.wait_group 2;" ::: "memory");
        else if (c == 1) asm volatile("cp.async.wait_group 1;" ::: "memory");
        else             asm volatile("cp.async.wait_group 0;" ::: "memory");
        __syncthreads();
        unsigned aB = smBase + c * STAGE_B;
        unsigned bB = aB + MAT_B;
        unsigned aAddr0 = aB + aRow * (RS * 2) + (lane >> 4) * 16;
        unsigned bAddr0 = bB + bRow * (RS * 2) + ((lane >> 3) & 1) * 16;
#pragma unroll
        for (int kk = 0; kk < 4; kk++) {
            unsigned koff = kk * 32;
            unsigned a[4][4], b[2][4];
#pragma unroll
            for (int mt = 0; mt < 4; mt++)
                ldsm4(a[mt][0], a[mt][1], a[mt][2], a[mt][3],
                      aAddr0 + mt * 16 * (RS * 2) + koff);
#pragma unroll
            for (int nh = 0; nh < 2; nh++)
                ldsm4(b[nh][0], b[nh][1], b[nh][2], b[nh][3],
                      bAddr0 + nh * 16 * (RS * 2) + koff);
#pragma unroll
            for (int mt = 0; mt < 4; mt++)
#pragma unroll
                for (int nt = 0; nt < 4; nt++)
                    mma16816(acc[mt][nt][0], acc[mt][nt][1], acc[mt][nt][2], acc[mt][nt][3],
                             a[mt][0], a[mt][1], a[mt][2], a[mt][3],
                             b[nt >> 1][(nt & 1) * 2], b[nt >> 1][(nt & 1) * 2 + 1]);
        }
    }

    // epilogue A: h1 fp16 stores
    int colBase = bn + warpN * 32;
#pragma unroll
    for (int mt = 0; mt < 4; mt++) {
        int row0 = bm + warpM * 64 + mt * 16 + (lane >> 2);
        int row1 = row0 + 8;
#pragma unroll
        for (int nt = 0; nt < 4; nt++) {
            int col = colBase + nt * 8 + (lane & 3) * 2;
            if (row0 < NN)
                *(__half2*)&g_h1h[(size_t)row0 * C1 + col] =
                    __floats2half2_rn(acc[mt][nt][0], acc[mt][nt][1]);
            if (row1 < NN)
                *(__half2*)&g_h1h[(size_t)row1 * C1 + col] =
                    __floats2half2_rn(acc[mt][nt][2], acc[mt][nt][3]);
        }
    }

    // epilogue B: attention logits -> interleaved exp factors
    int head = (bn >> 5) + warpN;
    float2 asv[4], adv[4];
#pragma unroll
    for (int nt = 0; nt < 4; nt++) {
        asv[nt] = *(const float2*)&a_s[head * 32 + nt * 8 + (lane & 3) * 2];
        adv[nt] = *(const float2*)&a_d[head * 32 + nt * 8 + (lane & 3) * 2];
    }
#pragma unroll
    for (int mt = 0; mt < 4; mt++) {
        float ps0 = 0.f, ps1 = 0.f, pd0 = 0.f, pd1 = 0.f;
#pragma unroll
        for (int nt = 0; nt < 4; nt++) {
            ps0 += acc[mt][nt][0] * asv[nt].x + acc[mt][nt][1] * asv[nt].y;
            ps1 += acc[mt][nt][2] * asv[nt].x + acc[mt][nt][3] * asv[nt].y;
            pd0 += acc[mt][nt][0] * adv[nt].x + acc[mt][nt][1] * adv[nt].y;
            pd1 += acc[mt][nt][2] * adv[nt].x + acc[mt][nt][3] * adv[nt].y;
        }
#pragma unroll
        for (int o = 1; o < 4; o <<= 1) {
            ps0 += __shfl_xor_sync(~0u, ps0, o);
            ps1 += __shfl_xor_sync(~0u, ps1, o);
            pd0 += __shfl_xor_sync(~0u, pd0, o);
            pd1 += __shfl_xor_sync(~0u, pd1, o);
        }
        if ((lane & 3) == 0) {
            int row0 = bm + warpM * 64 + mt * 16 + (lane >> 2);
            int row1 = row0 + 8;
            if (row0 < NN) {
                g_Es[row0 * 8 + head] = make_float2(__expf(ps0), __expf(0.2f * ps0));
                g_Ed[row0 * 8 + head] = make_float2(__expf(pd0), __expf(0.2f * pd0));
            }
            if (row1 < NN) {
                g_Es[row1 * 8 + head] = make_float2(__expf(ps1), __expf(0.2f * ps1));
                g_Ed[row1 * 8 + head] = make_float2(__expf(pd1), __expf(0.2f * pd1));
            }
        }
    }
}

// ---------------- launch 4 (ncu target): layer-1 aggregation, 4-edge pipeline ----------------
__global__ void __launch_bounds__(256) k_agg1(const float* __restrict__ b1,
                                              const float* __restrict__ W2,
                                              const float* __restrict__ as2,
                                              const float* __restrict__ ad2) {
    int d = (blockIdx.x * blockDim.x + threadIdx.x) >> 5;
    int lane = threadIdx.x & 31;
    if (d >= NN) return;
    int2 seg = g_seg[d];
    int beg = seg.x, end = seg.y;
    int h = lane >> 2;
    float2 Ed = g_Ed[d * 8 + h];

    float acc[8];
#pragma unroll
    for (int j = 0; j < 8; j++) acc[j] = 0.f;
    float z = 0.f;

    for (int base = beg; base < end; base += 32) {
        int cnt = min(32, end - base);
        int sv = g_csr[min(base + lane, end - 1)];
        int j = 0;
        for (; j + 4 <= cnt; j += 4) {
            int s0 = __shfl_sync(~0u, sv, j);
            int s1 = __shfl_sync(~0u, sv, j + 1);
            int s2 = __shfl_sync(~0u, sv, j + 2);
            int s3 = __shfl_sync(~0u, sv, j + 3);
            float2 E0 = g_Es[s0 * 8 + h];
            float2 E1 = g_Es[s1 * 8 + h];
            float2 E2 = g_Es[s2 * 8 + h];
            float2 E3 = g_Es[s3 * 8 + h];
            uint4 hv0 = *(const uint4*)&g_h1h[(size_t)s0 * C1 + lane * 8];
            uint4 hv1 = *(const uint4*)&g_h1h[(size_t)s1 * C1 + lane * 8];
            uint4 hv2 = *(const uint4*)&g_h1h[(size_t)s2 * C1 + lane * 8];
            uint4 hv3 = *(const uint4*)&g_h1h[(size_t)s3 * C1 + lane * 8];
            float ea0 = fmaxf(E0.x * Ed.x, E0.y * Ed.y);
            float ea1 = fmaxf(E1.x * Ed.x, E1.y * Ed.y);
            float ea2 = fmaxf(E2.x * Ed.x, E2.y * Ed.y);
            float ea3 = fmaxf(E3.x * Ed.x, E3.y * Ed.y);
            z += (ea0 + ea1) + (ea2 + ea3);
            __half2* p0 = (__half2*)&hv0;
            __half2* p1 = (__half2*)&hv1;
            __half2* p2 = (__half2*)&hv2;
            __half2* p3 = (__half2*)&hv3;
#pragma unroll
            for (int q = 0; q < 4; q++) {
                float2 f0 = __half22float2(p0[q]);
                float2 f1 = __half22float2(p1[q]);
                float2 f2 = __half22float2(p2[q]);
                float2 f3 = __half22float2(p3[q]);
                acc[2 * q]     += (ea0 * f0.x + ea1 * f1.x) + (ea2 * f2.x + ea3 * f3.x);
                acc[2 * q + 1] += (ea0 * f0.y + ea1 * f1.y) + (ea2 * f2.y + ea3 * f3.y);
            }
        }
        for (; j < cnt; j++) {
            int s0 = __shfl_sync(~0u, sv, j);
            float2 E0 = g_Es[s0 * 8 + h];
            uint4 hv0 = *(const uint4*)&g_h1h[(size_t)s0 * C1 + lane * 8];
            float ea0 = fmaxf(E0.x * Ed.x, E0.y * Ed.y);
            z += ea0;
            __half2* p0 = (__half2*)&hv0;
#pragma unroll
            for (int q = 0; q < 4; q++) {
                float2 f0 = __half22float2(p0[q]);
                acc[2 * q]     += ea0 * f0.x;
                acc[2 * q + 1] += ea0 * f0.y;
            }
        }
    }
    float inv = 1.f / (z + 1e-16f);

    float x1[8];
    float4 bA = *(const float4*)&b1[lane * 8];
    float4 bB = *(const float4*)&b1[lane * 8 + 4];
    float bb[8] = {bA.x, bA.y, bA.z, bA.w, bB.x, bB.y, bB.z, bB.w};
#pragma unroll
    for (int j = 0; j < 8; j++) {
        float v = acc[j] * inv + bb[j];
        x1[j] = v > 0.f ? v : __expf(v) - 1.f;
    }

    float p[8];
#pragma unroll
    for (int o = 0; o < 8; o++) p[o] = 0.f;
#pragma unroll
    for (int j = 0; j < 8; j++) {
        int c = lane * 8 + j;
        float4 w0 = *(const float4*)&W2[c * 8];
        float4 w1 = *(const float4*)&W2[c * 8 + 4];
        p[0] += x1[j] * w0.x; p[1] += x1[j] * w0.y;
        p[2] += x1[j] * w0.z; p[3] += x1[j] * w0.w;
        p[4] += x1[j] * w1.x; p[5] += x1[j] * w1.y;
        p[6] += x1[j] * w1.z; p[7] += x1[j] * w1.w;
    }
#pragma unroll
    for (int o = 0; o < 8; o++)
#pragma unroll
        for (int k = 16; k > 0; k >>= 1) p[o] += __shfl_xor_sync(~0u, p[o], k);

    float s2 = 0.f, d2 = 0.f;
#pragma unroll
    for (int o = 0; o < 8; o++) { s2 += p[o] * as2[o]; d2 += p[o] * ad2[o]; }
    if (lane == 0) {
        g_P[d] = make_float2(__expf(s2), __expf(0.2f * s2));
        g_Q[d] = make_float2(__expf(d2), __expf(0.2f * d2));
        *(float4*)&g_h2[d * 8]     = make_float4(p[0], p[1], p[2], p[3]);
        *(float4*)&g_h2[d * 8 + 4] = make_float4(p[4], p[5], p[6], p[7]);
        g_cnt[d] = 0;   // reset for next replay
    }
}

// ---------------- launch 5: layer-2 aggregation + log_softmax ----------------
__global__ void __launch_bounds__(256) k_agg2(const float* __restrict__ b2,
                                              float* __restrict__ out) {
    int d = (blockIdx.x * blockDim.x + threadIdx.x) >> 5;
    int lane = threadIdx.x & 31;
    if (d >= NN) return;
    int2 seg = g_seg[d];
    int beg = seg.x, end = seg.y;
    float2 q = g_Q[d];

    float z = 0.f, acc[8];
#pragma unroll
    for (int o = 0; o < 8; o++) acc[o] = 0.f;
    for (int e = beg + lane; e < end; e += 32) {
        int s = g_csr[e];
        float2 P = g_P[s];
        float ea = fmaxf(P.x * q.x, P.y * q.y);
        z += ea;
        const float4* hp = (const float4*)&g_h2[s * 8];
        float4 v0 = hp[0], v1 = hp[1];
        acc[0] += ea * v0.x; acc[1] += ea * v0.y; acc[2] += ea * v0.z; acc[3] += ea * v0.w;
        acc[4] += ea * v1.x; acc[5] += ea * v1.y; acc[6] += ea * v1.z; acc[7] += ea * v1.w;
    }
#pragma unroll
    for (int k = 16; k > 0; k >>= 1) z += __shfl_xor_sync(~0u, z, k);
#pragma unroll
    for (int o = 0; o < 8; o++)
#pragma unroll
        for (int k = 16; k > 0; k >>= 1) acc[o] += __shfl_xor_sync(~0u, acc[o], k);

    float inv = 1.f / (z + 1e-16f);
    float v[8], mx = -1e30f;
#pragma unroll
    for (int o = 0; o < 8; o++) { v[o] = acc[o] * inv + b2[o]; mx = fmaxf(mx, v[o]); }
    float se = 0.f;
#pragma unroll
    for (int o = 0; o < 8; o++) se += __expf(v[o] - mx);
    float lse = mx + __logf(se);
    if (lane == 0) {
        *(float4*)&out[d * 8]     = make_float4(v[0] - lse, v[1] - lse, v[2] - lse, v[3] - lse);
        *(float4*)&out[d * 8 + 4] = make_float4(v[4] - lse, v[5] - lse, v[6] - lse, v[7] - lse);
    }
}

// ---------------- launch ----------------
extern "C" void kernel_launch(void* const* d_in, const int* in_sizes, int n_in,
                              void* d_out, int out_size) {
    const float* high  = (const float*)d_in[0];
    const float* low   = (const float*)d_in[1];
    const int*   ei    = (const int*)d_in[2];
    const float* Wemb  = (const float*)d_in[3];
    const float* bemb  = (const float*)d_in[4];
    const float* W1    = (const float*)d_in[5];
    const float* asrc1 = (const float*)d_in[6];
    const float* adst1 = (const float*)d_in[7];
    const float* b1    = (const float*)d_in[8];
    const float* W2    = (const float*)d_in[9];
    const float* as2   = (const float*)d_in[10];
    const float* ad2   = (const float*)d_in[11];
    const float* b2    = (const float*)d_in[12];
    float* out = (float*)d_out;

    cudaFuncSetAttribute(k_gemm, cudaFuncAttributeMaxDynamicSharedMemorySize, SMEM_B);

    dim3 fb(192, 2);
    k_front<<<EMB_B + EDGE_B + W1T_B, fb>>>(high, low, Wemb, bemb, W1, ei);   // 1
    k_scan<<<1, 1024>>>();                                                    // 2
    k_gemm<<<GEMM_B + SCAT_B, 256, SMEM_B>>>(asrc1, adst1, ei);               // 3 (gemm + scatter)
    k_agg1<<<(NN + 7) / 8, 256>>>(b1, W2, as2, ad2);                          // 4 <- ncu
    k_agg2<<<(NN + 7) / 8, 256>>>(b2, out);                                   // 5
}